// round 1
// baseline (speedup 1.0000x reference)
#include <cuda_runtime.h>
#include <stdint.h>

// ReshapePagedCache: out = [k_cache_updated | v_cache_updated], fp32.
//   k, v:            [T=8192, H=32, D=128]
//   k_cache,v_cache: [NB=2048, H=32, BS=16, D=128]
//   slot_mapping:    [T] int32, slot = block*BS + off; negative => skip
//
// Output row (block,h,off,:) == cache row at the SAME linear offset, unless
// slot=block*16+off was written by some token t, in which case it is k[t,h,:].
// We build inv[slot] -> t once (scratch __device__ array), then do ONE fused
// streaming pass: 1 GiB read + 1 GiB write (the traffic floor).

#define NB          2048
#define HEADS       32
#define BS          16
#define HDIM        128
#define TOTAL_SLOTS (NB * BS)          // 32768
// float4 elements per cache: NB*HEADS*BS*HDIM/4 = 2^25
#define CACHE_F4    (NB * HEADS * BS * (HDIM / 4))

__device__ int g_inv[TOTAL_SLOTS];

__global__ void init_inv_kernel() {
    int i = blockIdx.x * blockDim.x + threadIdx.x;
    if (i < TOTAL_SLOTS) g_inv[i] = -1;
}

__global__ void scatter_inv_kernel(const int* __restrict__ slot_mapping, int T) {
    int t = blockIdx.x * blockDim.x + threadIdx.x;
    if (t < T) {
        int s = slot_mapping[t];
        if (s >= 0 && s < TOTAL_SLOTS) g_inv[s] = t;  // slots unique per spec
    }
}

__global__ void __launch_bounds__(256)
fused_cache_copy_kernel(const float4* __restrict__ k,
                        const float4* __restrict__ v,
                        const float4* __restrict__ k_cache,
                        const float4* __restrict__ v_cache,
                        float4* __restrict__ out_k,
                        float4* __restrict__ out_v) {
    unsigned i = blockIdx.x * blockDim.x + threadIdx.x;   // float4 index, < 2^25
    // Row decomposition (all power-of-two):
    //   i = ((block*HEADS + h)*BS + off)*32 + j   (32 float4 per 128-float row)
    unsigned j     = i & 31u;
    unsigned row   = i >> 5;          // (block*32 + h)*16 + off
    unsigned off   = row & 15u;
    unsigned h     = (row >> 4) & 31u;
    unsigned block = row >> 9;

    int t = g_inv[(block << 4) | off];   // one load per warp, warp-uniform

    float4 kv, vv;
    if (t >= 0) {
        unsigned src = ((unsigned)t * (unsigned)HEADS + h) * 32u + j;  // k[t,h,:]
        kv = k[src];
        vv = v[src];
    } else {
        kv = k_cache[i];                  // identical linear layout
        vv = v_cache[i];
    }
    out_k[i] = kv;
    out_v[i] = vv;
}

extern "C" void kernel_launch(void* const* d_in, const int* in_sizes, int n_in,
                              void* d_out, int out_size) {
    const float4* k        = (const float4*)d_in[0];
    const float4* v        = (const float4*)d_in[1];
    const float4* k_cache  = (const float4*)d_in[2];
    const float4* v_cache  = (const float4*)d_in[3];
    const int*    slots    = (const int*)d_in[4];
    const int T = in_sizes[4];

    float4* out_k = (float4*)d_out;
    float4* out_v = out_k + CACHE_F4;

    init_inv_kernel<<<(TOTAL_SLOTS + 255) / 256, 256>>>();
    scatter_inv_kernel<<<(T + 255) / 256, 256>>>(slots, T);
    fused_cache_copy_kernel<<<CACHE_F4 / 256, 256>>>(k, v, k_cache, v_cache,
                                                     out_k, out_v);
}

// round 3
// speedup vs baseline: 1.0075x; 1.0075x over previous
#include <cuda_runtime.h>
#include <stdint.h>

// ReshapePagedCache: out = [k_cache_updated | v_cache_updated], fp32.
//   k, v:            [T=8192, H=32, D=128]
//   k_cache,v_cache: [NB=2048, H=32, BS=16, D=128]
//   slot_mapping:    [T] int32, slot = block*BS + off; negative => skip
//
// Output row (block,h,off,:) == cache row at the SAME linear offset, unless
// slot=block*16+off was written by token t, in which case it is k[t,h,:].
// inv[slot] -> t built once in scratch; then ONE fused streaming pass:
// 1 GiB read + 1 GiB write (the traffic floor). Streaming .cs hints
// (zero-reuse stream, keep it out of L2 residency) + ILP=2 per thread.

#define NB          2048
#define HEADS       32
#define BS          16
#define HDIM        128
#define TOTAL_SLOTS (NB * BS)                    // 32768
#define CACHE_F4    (NB * HEADS * BS * (HDIM/4)) // 2^25 float4 per cache
#define HALF_F4     (CACHE_F4 / 2)

__device__ int g_inv[TOTAL_SLOTS];

__global__ void init_inv_kernel() {
    // int4-vectorized: 32768 ints = 8192 int4
    int i = blockIdx.x * blockDim.x + threadIdx.x;
    if (i < TOTAL_SLOTS / 4)
        ((int4*)g_inv)[i] = make_int4(-1, -1, -1, -1);
}

__global__ void scatter_inv_kernel(const int* __restrict__ slot_mapping, int T) {
    int t = blockIdx.x * blockDim.x + threadIdx.x;
    if (t < T) {
        int s = slot_mapping[t];
        if (s >= 0 && s < TOTAL_SLOTS) g_inv[s] = t;  // slots unique per spec
    }
}

__device__ __forceinline__ void process_one(unsigned i,
                                            const float4* __restrict__ k,
                                            const float4* __restrict__ v,
                                            const float4* __restrict__ k_cache,
                                            const float4* __restrict__ v_cache,
                                            float4* __restrict__ out_k,
                                            float4* __restrict__ out_v) {
    // i = ((block*HEADS + h)*BS + off)*32 + j   (32 float4 per 128-float row)
    unsigned j     = i & 31u;
    unsigned row   = i >> 5;
    unsigned off   = row & 15u;
    unsigned h     = (row >> 4) & 31u;
    unsigned block = row >> 9;

    int t = g_inv[(block << 4) | off];   // warp-uniform, L2-hot (128 KB table)

    float4 kv, vv;
    if (t >= 0) {
        unsigned src = ((unsigned)t * (unsigned)HEADS + h) * 32u + j;
        kv = __ldcs(&k[src]);
        vv = __ldcs(&v[src]);
    } else {
        kv = __ldcs(&k_cache[i]);
        vv = __ldcs(&v_cache[i]);
    }
    __stcs(&out_k[i], kv);
    __stcs(&out_v[i], vv);
}

__global__ void __launch_bounds__(256)
fused_cache_copy_kernel(const float4* __restrict__ k,
                        const float4* __restrict__ v,
                        const float4* __restrict__ k_cache,
                        const float4* __restrict__ v_cache,
                        float4* __restrict__ out_k,
                        float4* __restrict__ out_v) {
    unsigned i = blockIdx.x * blockDim.x + threadIdx.x;   // < HALF_F4
    // Two independent streams HALF_F4 apart -> 4 outstanding loads/thread.
    process_one(i,           k, v, k_cache, v_cache, out_k, out_v);
    process_one(i + HALF_F4, k, v, k_cache, v_cache, out_k, out_v);
}

extern "C" void kernel_launch(void* const* d_in, const int* in_sizes, int n_in,
                              void* d_out, int out_size) {
    const float4* k        = (const float4*)d_in[0];
    const float4* v        = (const float4*)d_in[1];
    const float4* k_cache  = (const float4*)d_in[2];
    const float4* v_cache  = (const float4*)d_in[3];
    const int*    slots    = (const int*)d_in[4];
    const int T = in_sizes[4];

    float4* out_k = (float4*)d_out;
    float4* out_v = out_k + CACHE_F4;

    init_inv_kernel<<<TOTAL_SLOTS / 4 / 256, 256>>>();   // 8192/256 = 32 blocks
    scatter_inv_kernel<<<(T + 255) / 256, 256>>>(slots, T);
    fused_cache_copy_kernel<<<HALF_F4 / 256, 256>>>(k, v, k_cache, v_cache,
                                                    out_k, out_v);
}